// round 4
// baseline (speedup 1.0000x reference)
#include <cuda_runtime.h>
#include <cuda_bf16.h>
#include <math.h>
#include <stdint.h>

#define N_NODES 65536
#define N_EDGES 524288
#define HIDDEN 128
#define OUTDIM 10
#define NUM_GRAPHS 64
#define SLOT_CAP 64

// ---------------- scratch (device globals; no allocation allowed) ----------
__device__ __align__(16) static float g_ahi[(size_t)N_NODES * HIDDEN];
__device__ __align__(16) static float g_alo[(size_t)N_NODES * HIDDEN];
__device__ __align__(16) static float g_h[(size_t)N_NODES * HIDDEN];
__device__ static int      g_deg[N_NODES];
__device__ static int      g_slots[(size_t)N_NODES * SLOT_CAP];
__device__ static float    g_gsum[NUM_GRAPHS * HIDDEN];
__device__ static float    g_gcnt[NUM_GRAPHS];
__device__ static int      g_is64;
// W splits: [layer][n*128 + permuted k], tf32 bits
__device__ __align__(16) static uint32_t g_whi[3][HIDDEN * HIDDEN];
__device__ __align__(16) static uint32_t g_wlo[3][HIDDEN * HIDDEN];

// ---------------- helpers ----------------------------------------------------
__device__ __forceinline__ void tf32_split(float v, uint32_t& hb, uint32_t& lb) {
    asm("cvt.rna.tf32.f32 %0, %1;" : "=r"(hb) : "f"(v));
    float r = v - __uint_as_float(hb);
    asm("cvt.rna.tf32.f32 %0, %1;" : "=r"(lb) : "f"(r));
}

__device__ __forceinline__ void mma_tf32(float* c,
                                         uint32_t a0, uint32_t a1, uint32_t a2, uint32_t a3,
                                         uint32_t b0, uint32_t b1) {
    asm volatile(
        "mma.sync.aligned.m16n8k8.row.col.f32.tf32.tf32.f32 "
        "{%0,%1,%2,%3}, {%4,%5,%6,%7}, {%8,%9}, {%0,%1,%2,%3};"
        : "+f"(c[0]), "+f"(c[1]), "+f"(c[2]), "+f"(c[3])
        : "r"(a0), "r"(a1), "r"(a2), "r"(a3), "r"(b0), "r"(b1));
}

// ---------------- index dtype detection ------------------------------------
__global__ void detect_kernel(const unsigned int* __restrict__ w) {
    bool is64 = true;
    for (int i = 1; i < 256; i += 2) {
        if (w[i] != 0u) { is64 = false; break; }
    }
    g_is64 = is64 ? 1 : 0;
}

__device__ __forceinline__ int load_idx(const void* p, int i, int is64) {
    if (is64) return (int)((const long long*)p)[i];
    return ((const int*)p)[i];
}

// ---------------- zero scratch ----------------------------------------------
__global__ void zero_kernel() {
    int i = blockIdx.x * blockDim.x + threadIdx.x;
    if (i < N_NODES) g_deg[i] = 0;
    if (i < NUM_GRAPHS * HIDDEN) g_gsum[i] = 0.0f;
    if (i < NUM_GRAPHS) g_gcnt[i] = 0.0f;
}

// ---------------- W prep: split + transpose + k-octet permute ----------------
// Storage: g_whi[layer][n*128 + pos(k)] where pos(k) pairs (k0+t, k0+t+4)
// into adjacent words for LDG.64 B-fragment loads.
__global__ void wprep_kernel(const float* __restrict__ W1,
                             const float* __restrict__ W2,
                             const float* __restrict__ W3) {
    int i = blockIdx.x * blockDim.x + threadIdx.x;
    if (i >= 3 * HIDDEN * HIDDEN) return;
    int layer = i >> 14;
    int idx = i & (HIDDEN * HIDDEN - 1);
    const float* W = (layer == 0) ? W1 : (layer == 1) ? W2 : W3;
    int k = idx >> 7, n = idx & 127;           // W[k][n], coalesced read
    float w = __ldg(W + idx);
    uint32_t hb, lb;
    tf32_split(w, hb, lb);
    int pos = (k & ~7) | (((k & 3) << 1) | ((k >> 2) & 1));
    g_whi[layer][n * HIDDEN + pos] = hb;
    g_wlo[layer][n * HIDDEN + pos] = lb;
}

// ---------------- bucketed inverse adjacency ---------------------------------
__global__ void build_kernel(const void* __restrict__ src,
                             const void* __restrict__ dst) {
    int e = blockIdx.x * blockDim.x + threadIdx.x;
    if (e >= N_EDGES) return;
    int is64 = g_is64;
    int d = load_idx(dst, e, is64);
    int s = load_idx(src, e, is64);
    int pos = atomicAdd(&g_deg[d], 1);
    if (pos < SLOT_CAP) g_slots[(size_t)d * SLOT_CAP + pos] = s;
}

// ---------------- per-node gather-sum, emits tf32 hi/lo split -----------------
__global__ void gather_kernel(const float* __restrict__ hin,
                              float* __restrict__ ahi,
                              float* __restrict__ alo) {
    int w = (blockIdx.x * blockDim.x + threadIdx.x) >> 5;
    int lane = threadIdx.x & 31;
    if (w >= N_NODES) return;
    int deg = g_deg[w];
    if (deg > SLOT_CAP) deg = SLOT_CAP;
    const int* slots = g_slots + (size_t)w * SLOT_CAP;
    int s0 = (lane < deg) ? slots[lane] : 0;
    int s1 = (32 + lane < deg) ? slots[32 + lane] : 0;
    float4 acc = make_float4(0.f, 0.f, 0.f, 0.f);
    for (int i = 0; i < deg; i++) {
        int s = __shfl_sync(0xffffffffu, (i < 32) ? s0 : s1, i & 31);
        float4 v = __ldg((const float4*)(hin + (size_t)s * HIDDEN) + lane);
        acc.x += v.x; acc.y += v.y; acc.z += v.z; acc.w += v.w;
    }
    uint32_t hx, lx, hy, ly, hz, lz, hw, lw;
    tf32_split(acc.x, hx, lx);
    tf32_split(acc.y, hy, ly);
    tf32_split(acc.z, hz, lz);
    tf32_split(acc.w, hw, lw);
    float4 hi = make_float4(__uint_as_float(hx), __uint_as_float(hy),
                            __uint_as_float(hz), __uint_as_float(hw));
    float4 lo = make_float4(__uint_as_float(lx), __uint_as_float(ly),
                            __uint_as_float(lz), __uint_as_float(lw));
    ((float4*)(ahi + (size_t)w * HIDDEN))[lane] = hi;
    ((float4*)(alo + (size_t)w * HIDDEN))[lane] = lo;
}

// ---------------- SMEM-free TF32 mma GEMM -------------------------------------
// CTA = 128 rows x 128 cols, 256 threads = 8 warps (2M x 4N), warp tile 64x32.
// All fragments loaded directly from global (A/W splits precomputed).
#define f2u __float_as_uint

__global__ void __launch_bounds__(256, 2)
gemm_tc_kernel(const float* __restrict__ Ahi, const float* __restrict__ Alo,
               const uint32_t* __restrict__ Wh, const uint32_t* __restrict__ Wl,
               const float* __restrict__ b, float* __restrict__ out) {
    int tid = threadIdx.x;
    int lane = tid & 31, wid = tid >> 5;
    int gq = lane >> 2, tq = lane & 3;
    int warp_m = wid & 1, warp_n = wid >> 1;
    const int mBase = warp_m * 64;
    const int nBase = warp_n * 32;
    size_t rowBase = (size_t)blockIdx.x * 128;

    float acc[4][4][4];
#pragma unroll
    for (int mi = 0; mi < 4; mi++)
#pragma unroll
        for (int ni = 0; ni < 4; ni++)
#pragma unroll
            for (int r = 0; r < 4; r++) acc[mi][ni][r] = 0.0f;

    const float* ahp[4];
    const float* alp[4];
#pragma unroll
    for (int mi = 0; mi < 4; mi++) {
        size_t r = rowBase + mBase + mi * 16 + gq;
        ahp[mi] = Ahi + r * HIDDEN;
        alp[mi] = Alo + r * HIDDEN;
    }
    const uint2* bhp[4];
    const uint2* blp[4];
#pragma unroll
    for (int ni = 0; ni < 4; ni++) {
        int c = nBase + ni * 8 + gq;
        bhp[ni] = (const uint2*)(Wh + c * HIDDEN);
        blp[ni] = (const uint2*)(Wl + c * HIDDEN);
    }

#pragma unroll 4
    for (int ks = 0; ks < 16; ks++) {
        int k0 = ks * 8;
        uint32_t ah[4][4], al[4][4];
#pragma unroll
        for (int mi = 0; mi < 4; mi++) {
            ah[mi][0] = f2u(__ldg(ahp[mi] + k0 + tq));
            ah[mi][1] = f2u(__ldg(ahp[mi] + 8 * HIDDEN + k0 + tq));
            ah[mi][2] = f2u(__ldg(ahp[mi] + k0 + tq + 4));
            ah[mi][3] = f2u(__ldg(ahp[mi] + 8 * HIDDEN + k0 + tq + 4));
            al[mi][0] = f2u(__ldg(alp[mi] + k0 + tq));
            al[mi][1] = f2u(__ldg(alp[mi] + 8 * HIDDEN + k0 + tq));
            al[mi][2] = f2u(__ldg(alp[mi] + k0 + tq + 4));
            al[mi][3] = f2u(__ldg(alp[mi] + 8 * HIDDEN + k0 + tq + 4));
        }
        uint2 bh[4], bl[4];
#pragma unroll
        for (int ni = 0; ni < 4; ni++) {
            bh[ni] = __ldg(bhp[ni] + (k0 >> 1) + tq);
            bl[ni] = __ldg(blp[ni] + (k0 >> 1) + tq);
        }
#pragma unroll
        for (int mi = 0; mi < 4; mi++)
#pragma unroll
            for (int ni = 0; ni < 4; ni++) {
                mma_tf32(acc[mi][ni], ah[mi][0], ah[mi][1], ah[mi][2], ah[mi][3],
                         bh[ni].x, bh[ni].y);
                mma_tf32(acc[mi][ni], ah[mi][0], ah[mi][1], ah[mi][2], ah[mi][3],
                         bl[ni].x, bl[ni].y);
                mma_tf32(acc[mi][ni], al[mi][0], al[mi][1], al[mi][2], al[mi][3],
                         bh[ni].x, bh[ni].y);
            }
    }

    // ---- epilogue: bias + ELU + store (layout proven in round 3) ----
#pragma unroll
    for (int mi = 0; mi < 4; mi++) {
        int r0 = mBase + mi * 16 + gq;
#pragma unroll
        for (int ni = 0; ni < 4; ni++) {
            int c0 = nBase + ni * 8 + 2 * tq;
            float2 bb = __ldg((const float2*)(b + c0));
            float v0 = acc[mi][ni][0] + bb.x;
            float v1 = acc[mi][ni][1] + bb.y;
            float v2 = acc[mi][ni][2] + bb.x;
            float v3 = acc[mi][ni][3] + bb.y;
            v0 = v0 > 0.f ? v0 : expm1f(v0);
            v1 = v1 > 0.f ? v1 : expm1f(v1);
            v2 = v2 > 0.f ? v2 : expm1f(v2);
            v3 = v3 > 0.f ? v3 : expm1f(v3);
            *(float2*)(out + (rowBase + r0) * HIDDEN + c0) = make_float2(v0, v1);
            *(float2*)(out + (rowBase + r0 + 8) * HIDDEN + c0) = make_float2(v2, v3);
        }
    }
}

// ---------------- graph readout ----------------------------------------------
__global__ void count_kernel(const void* __restrict__ gid) {
    int i = blockIdx.x * blockDim.x + threadIdx.x;
    if (i >= N_NODES) return;
    int g = load_idx(gid, i, g_is64);
    atomicAdd(&g_gcnt[g], 1.0f);
}

__global__ void readout_kernel(const float* __restrict__ h,
                               const void* __restrict__ gid) {
    int t = threadIdx.x;
    int base = blockIdx.x * 128;
    int is64 = g_is64;
    int cur = load_idx(gid, base, is64);
    float acc = 0.0f;
    for (int n = 0; n < 128; n++) {
        int node = base + n;
        int g = load_idx(gid, node, is64);
        if (g != cur) {
            atomicAdd(&g_gsum[cur * HIDDEN + t], acc);
            acc = 0.0f; cur = g;
        }
        acc += h[(size_t)node * HIDDEN + t];
    }
    atomicAdd(&g_gsum[cur * HIDDEN + t], acc);
}

__global__ void classifier_kernel(const float* __restrict__ Wc,
                                  const float* __restrict__ bc,
                                  float* __restrict__ out) {
    int t = blockIdx.x * blockDim.x + threadIdx.x;
    if (t >= NUM_GRAPHS * OUTDIM) return;
    int g = t / OUTDIM, o = t % OUTDIM;
    float c = fmaxf(g_gcnt[g], 1.0f);
    float inv = 1.0f / c;
    float acc = bc[o];
#pragma unroll 8
    for (int k = 0; k < HIDDEN; k++)
        acc += g_gsum[g * HIDDEN + k] * inv * Wc[k * OUTDIM + o];
    out[t] = acc;
}

// ---------------- launch -------------------------------------------------------
extern "C" void kernel_launch(void* const* d_in, const int* in_sizes, int n_in,
                              void* d_out, int out_size) {
    const float* features = (const float*)d_in[0];
    const void*  src      = d_in[1];
    const void*  dst      = d_in[2];
    const void*  gids     = d_in[3];
    const float* W1 = (const float*)d_in[4];
    const float* b1 = (const float*)d_in[5];
    const float* W2 = (const float*)d_in[6];
    const float* b2 = (const float*)d_in[7];
    const float* W3 = (const float*)d_in[8];
    const float* b3 = (const float*)d_in[9];
    const float* Wc = (const float*)d_in[10];
    const float* bc = (const float*)d_in[11];
    float* out = (float*)d_out;

    float* ahi; cudaGetSymbolAddress((void**)&ahi, g_ahi);
    float* alo; cudaGetSymbolAddress((void**)&alo, g_alo);
    float* h;   cudaGetSymbolAddress((void**)&h, g_h);
    uint32_t* whi; cudaGetSymbolAddress((void**)&whi, g_whi);
    uint32_t* wlo; cudaGetSymbolAddress((void**)&wlo, g_wlo);

    detect_kernel<<<1, 1>>>((const unsigned int*)src);
    zero_kernel<<<N_NODES / 256, 256>>>();
    wprep_kernel<<<(3 * HIDDEN * HIDDEN) / 256, 256>>>(W1, W2, W3);
    build_kernel<<<N_EDGES / 256, 256>>>(src, dst);

    const int GATHER_BLOCKS = (N_NODES * 32) / 256;
    const int GEMM_BLOCKS = N_NODES / 128;
    const int WSZ = HIDDEN * HIDDEN;

    gather_kernel<<<GATHER_BLOCKS, 256>>>(features, ahi, alo);
    gemm_tc_kernel<<<GEMM_BLOCKS, 256>>>(ahi, alo, whi, wlo, b1, h);
    gather_kernel<<<GATHER_BLOCKS, 256>>>(h, ahi, alo);
    gemm_tc_kernel<<<GEMM_BLOCKS, 256>>>(ahi, alo, whi + WSZ, wlo + WSZ, b2, h);
    gather_kernel<<<GATHER_BLOCKS, 256>>>(h, ahi, alo);
    gemm_tc_kernel<<<GEMM_BLOCKS, 256>>>(ahi, alo, whi + 2 * WSZ, wlo + 2 * WSZ, b3, h);

    count_kernel<<<N_NODES / 256, 256>>>(gids);
    readout_kernel<<<N_NODES / 128, 128>>>(h, gids);
    classifier_kernel<<<1, NUM_GRAPHS * OUTDIM>>>(Wc, bc, out);
}

// round 5
// speedup vs baseline: 1.6514x; 1.6514x over previous
#include <cuda_runtime.h>
#include <cuda_bf16.h>
#include <math.h>
#include <stdint.h>

#define N_NODES 65536
#define N_EDGES 524288
#define HIDDEN 128
#define OUTDIM 10
#define NUM_GRAPHS 64
#define SLOT_CAP 64

// ---------------- scratch (device globals; no allocation allowed) ----------
// A planes: bf16 pairs, k-word-permuted, 64 words (128 bf16) per node row.
__device__ __align__(16) static uint32_t g_ahi[(size_t)N_NODES * 64];
__device__ __align__(16) static uint32_t g_alo[(size_t)N_NODES * 64];
__device__ __align__(16) static float    g_h[(size_t)N_NODES * HIDDEN];
__device__ static int      g_deg[N_NODES];
__device__ static int      g_slots[(size_t)N_NODES * SLOT_CAP];
__device__ static float    g_gsum[NUM_GRAPHS * HIDDEN];
__device__ static float    g_gcnt[NUM_GRAPHS];
__device__ static int      g_is64;
// W planes: [layer][n][permuted k word], bf16 pairs
__device__ __align__(16) static uint32_t g_whi[3][HIDDEN * 64];
__device__ __align__(16) static uint32_t g_wlo[3][HIDDEN * 64];

// ---------------- helpers ----------------------------------------------------
// permuted position of word w (word = 2 bf16 along k) within its 8-word group
__device__ __forceinline__ int kperm(int w) {
    return (w & ~7) | (((w & 3) << 1) | ((w >> 2) & 1));
}

__device__ __forceinline__ void bf16_split(float v, uint16_t& h, uint16_t& l) {
    __nv_bfloat16 hb = __float2bfloat16(v);
    float r = v - __bfloat162float(hb);
    __nv_bfloat16 lb = __float2bfloat16(r);
    h = __bfloat16_as_ushort(hb);
    l = __bfloat16_as_ushort(lb);
}

__device__ __forceinline__ void mma_bf16(float* c, uint32_t a0, uint32_t a1,
                                         uint32_t a2, uint32_t a3,
                                         uint32_t b0, uint32_t b1) {
    asm volatile(
        "mma.sync.aligned.m16n8k16.row.col.f32.bf16.bf16.f32 "
        "{%0,%1,%2,%3}, {%4,%5,%6,%7}, {%8,%9}, {%0,%1,%2,%3};"
        : "+f"(c[0]), "+f"(c[1]), "+f"(c[2]), "+f"(c[3])
        : "r"(a0), "r"(a1), "r"(a2), "r"(a3), "r"(b0), "r"(b1));
}

// ---------------- index dtype detection ------------------------------------
__global__ void detect_kernel(const unsigned int* __restrict__ w) {
    bool is64 = true;
    for (int i = 1; i < 256; i += 2) {
        if (w[i] != 0u) { is64 = false; break; }
    }
    g_is64 = is64 ? 1 : 0;
}

__device__ __forceinline__ int load_idx(const void* p, int i, int is64) {
    if (is64) return (int)((const long long*)p)[i];
    return ((const int*)p)[i];
}

// ---------------- zero scratch ----------------------------------------------
__global__ void zero_kernel() {
    int i = blockIdx.x * blockDim.x + threadIdx.x;
    if (i < N_NODES) g_deg[i] = 0;
    if (i < NUM_GRAPHS * HIDDEN) g_gsum[i] = 0.0f;
    if (i < NUM_GRAPHS) g_gcnt[i] = 0.0f;
}

// ---------------- W prep: split + transpose + k-word permute -----------------
// thread handles one (layer, n, word) -> reads W[2w][n], W[2w+1][n]
__global__ void wprep_kernel(const float* __restrict__ W1,
                             const float* __restrict__ W2,
                             const float* __restrict__ W3) {
    int i = blockIdx.x * blockDim.x + threadIdx.x;
    if (i >= 3 * HIDDEN * 64) return;
    int layer = i / (HIDDEN * 64);
    int rem = i - layer * (HIDDEN * 64);
    int n = rem >> 6, w = rem & 63;
    const float* W = (layer == 0) ? W1 : (layer == 1) ? W2 : W3;
    float v0 = __ldg(W + (2 * w) * HIDDEN + n);
    float v1 = __ldg(W + (2 * w + 1) * HIDDEN + n);
    uint16_t h0, l0, h1, l1;
    bf16_split(v0, h0, l0);
    bf16_split(v1, h1, l1);
    int pos = n * 64 + kperm(w);
    g_whi[layer][pos] = (uint32_t)h0 | ((uint32_t)h1 << 16);
    g_wlo[layer][pos] = (uint32_t)l0 | ((uint32_t)l1 << 16);
}

// ---------------- bucketed inverse adjacency (4 edges/thread for MLP) --------
__global__ void build_kernel(const void* __restrict__ src,
                             const void* __restrict__ dst) {
    int base = (blockIdx.x * blockDim.x + threadIdx.x) * 4;
    if (base >= N_EDGES) return;
    int is64 = g_is64;
    int d0 = load_idx(dst, base + 0, is64), s0 = load_idx(src, base + 0, is64);
    int d1 = load_idx(dst, base + 1, is64), s1 = load_idx(src, base + 1, is64);
    int d2 = load_idx(dst, base + 2, is64), s2 = load_idx(src, base + 2, is64);
    int d3 = load_idx(dst, base + 3, is64), s3 = load_idx(src, base + 3, is64);
    int p0 = atomicAdd(&g_deg[d0], 1);
    int p1 = atomicAdd(&g_deg[d1], 1);
    int p2 = atomicAdd(&g_deg[d2], 1);
    int p3 = atomicAdd(&g_deg[d3], 1);
    if (p0 < SLOT_CAP) g_slots[(size_t)d0 * SLOT_CAP + p0] = s0;
    if (p1 < SLOT_CAP) g_slots[(size_t)d1 * SLOT_CAP + p1] = s1;
    if (p2 < SLOT_CAP) g_slots[(size_t)d2 * SLOT_CAP + p2] = s2;
    if (p3 < SLOT_CAP) g_slots[(size_t)d3 * SLOT_CAP + p3] = s3;
}

// ---------------- gather-sum -> bf16 hi/lo planes (k-word permuted) ----------
__global__ void gather_kernel(const float* __restrict__ hin,
                              uint32_t* __restrict__ ahi,
                              uint32_t* __restrict__ alo) {
    int w = (blockIdx.x * blockDim.x + threadIdx.x) >> 5;
    int lane = threadIdx.x & 31;
    if (w >= N_NODES) return;
    int deg = g_deg[w];
    if (deg > SLOT_CAP) deg = SLOT_CAP;
    const int* slots = g_slots + (size_t)w * SLOT_CAP;
    int s0 = (lane < deg) ? slots[lane] : 0;
    int s1 = (32 + lane < deg) ? slots[32 + lane] : 0;
    float4 acc = make_float4(0.f, 0.f, 0.f, 0.f);
    for (int i = 0; i < deg; i++) {
        int s = __shfl_sync(0xffffffffu, (i < 32) ? s0 : s1, i & 31);
        float4 v = __ldg((const float4*)(hin + (size_t)s * HIDDEN) + lane);
        acc.x += v.x; acc.y += v.y; acc.z += v.z; acc.w += v.w;
    }
    // lane holds k = 4*lane .. 4*lane+3  ->  words w0=2*lane (x,y), w1=2*lane+1 (z,w)
    uint16_t hx, lx, hy, ly, hz, lz, hw, lw;
    bf16_split(acc.x, hx, lx);
    bf16_split(acc.y, hy, ly);
    bf16_split(acc.z, hz, lz);
    bf16_split(acc.w, hw, lw);
    size_t rowOff = (size_t)w * 64;
    int p0 = kperm(2 * lane), p1 = kperm(2 * lane + 1);
    ahi[rowOff + p0] = (uint32_t)hx | ((uint32_t)hy << 16);
    ahi[rowOff + p1] = (uint32_t)hz | ((uint32_t)hw << 16);
    alo[rowOff + p0] = (uint32_t)lx | ((uint32_t)ly << 16);
    alo[rowOff + p1] = (uint32_t)lz | ((uint32_t)lw << 16);
}

// ---------------- bf16x3 mma GEMM: 64 rows x 128 cols per CTA -----------------
// 256 threads = 8 warps (2M x 4N), warp tile 32x32 (mi=2 m16, ni=4 n8).
// SMEM strides of 68 words -> conflict-free LDS.64 fragment loads.
#define AS_STR 68
#define SM_AH 0
#define SM_AL (64 * AS_STR)
#define SM_WH (2 * 64 * AS_STR)
#define SM_WL (2 * 64 * AS_STR + 128 * AS_STR)
#define GEMM_SMEM_WORDS (2 * 64 * AS_STR + 2 * 128 * AS_STR)
#define GEMM_SMEM_BYTES (GEMM_SMEM_WORDS * 4)

__global__ void __launch_bounds__(256, 2)
gemm_tc_kernel(const uint32_t* __restrict__ Ahi, const uint32_t* __restrict__ Alo,
               const uint32_t* __restrict__ Wh, const uint32_t* __restrict__ Wl,
               const float* __restrict__ b, float* __restrict__ out) {
    extern __shared__ __align__(16) uint32_t smem[];
    int tid = threadIdx.x;
    int lane = tid & 31, wid = tid >> 5;
    int gq = lane >> 2, tq = lane & 3;
    int warp_m = wid & 1, warp_n = wid >> 1;
    const int mBase = warp_m * 32;
    const int nBase = warp_n * 32;
    size_t rowBase = (size_t)blockIdx.x * 64;

    // ---- stage A planes: 64 rows x 16 uint4 each ----
    {
        const uint4* src_h = (const uint4*)(Ahi + rowBase * 64);
        const uint4* src_l = (const uint4*)(Alo + rowBase * 64);
        for (int i = tid; i < 64 * 16; i += 256) {
            int r = i >> 4, c4 = i & 15;
            *(uint4*)(smem + SM_AH + r * AS_STR + c4 * 4) = __ldg(src_h + i);
            *(uint4*)(smem + SM_AL + r * AS_STR + c4 * 4) = __ldg(src_l + i);
        }
    }
    // ---- stage W planes: 128 cols x 16 uint4 each ----
    {
        const uint4* src_h = (const uint4*)Wh;
        const uint4* src_l = (const uint4*)Wl;
        for (int i = tid; i < 128 * 16; i += 256) {
            int n = i >> 4, c4 = i & 15;
            *(uint4*)(smem + SM_WH + n * AS_STR + c4 * 4) = __ldg(src_h + i);
            *(uint4*)(smem + SM_WL + n * AS_STR + c4 * 4) = __ldg(src_l + i);
        }
    }
    __syncthreads();

    float acc[2][4][4];
#pragma unroll
    for (int mi = 0; mi < 2; mi++)
#pragma unroll
        for (int ni = 0; ni < 4; ni++)
#pragma unroll
            for (int r = 0; r < 4; r++) acc[mi][ni][r] = 0.0f;

#pragma unroll
    for (int ks = 0; ks < 8; ks++) {
        int kw = ks * 8 + 2 * tq;
        uint2 ah[2][2], al[2][2];   // [mi][rowhalf] = (a0,a2)/(a1,a3)
#pragma unroll
        for (int mi = 0; mi < 2; mi++) {
            int r = mBase + mi * 16 + gq;
            ah[mi][0] = *(const uint2*)(smem + SM_AH + r * AS_STR + kw);
            ah[mi][1] = *(const uint2*)(smem + SM_AH + (r + 8) * AS_STR + kw);
            al[mi][0] = *(const uint2*)(smem + SM_AL + r * AS_STR + kw);
            al[mi][1] = *(const uint2*)(smem + SM_AL + (r + 8) * AS_STR + kw);
        }
        uint2 bh[4], bl[4];
#pragma unroll
        for (int ni = 0; ni < 4; ni++) {
            int c = nBase + ni * 8 + gq;
            bh[ni] = *(const uint2*)(smem + SM_WH + c * AS_STR + kw);
            bl[ni] = *(const uint2*)(smem + SM_WL + c * AS_STR + kw);
        }
#pragma unroll
        for (int mi = 0; mi < 2; mi++)
#pragma unroll
            for (int ni = 0; ni < 4; ni++) {
                mma_bf16(acc[mi][ni], ah[mi][0].x, ah[mi][1].x, ah[mi][0].y, ah[mi][1].y,
                         bh[ni].x, bh[ni].y);
                mma_bf16(acc[mi][ni], ah[mi][0].x, ah[mi][1].x, ah[mi][0].y, ah[mi][1].y,
                         bl[ni].x, bl[ni].y);
                mma_bf16(acc[mi][ni], al[mi][0].x, al[mi][1].x, al[mi][0].y, al[mi][1].y,
                         bh[ni].x, bh[ni].y);
            }
    }

    // ---- epilogue: bias + ELU + store ----
#pragma unroll
    for (int mi = 0; mi < 2; mi++) {
        int r0 = mBase + mi * 16 + gq;
#pragma unroll
        for (int ni = 0; ni < 4; ni++) {
            int c0 = nBase + ni * 8 + 2 * tq;
            float2 bb = __ldg((const float2*)(b + c0));
            float v0 = acc[mi][ni][0] + bb.x;
            float v1 = acc[mi][ni][1] + bb.y;
            float v2 = acc[mi][ni][2] + bb.x;
            float v3 = acc[mi][ni][3] + bb.y;
            v0 = v0 > 0.f ? v0 : expm1f(v0);
            v1 = v1 > 0.f ? v1 : expm1f(v1);
            v2 = v2 > 0.f ? v2 : expm1f(v2);
            v3 = v3 > 0.f ? v3 : expm1f(v3);
            *(float2*)(out + (rowBase + r0) * HIDDEN + c0) = make_float2(v0, v1);
            *(float2*)(out + (rowBase + r0 + 8) * HIDDEN + c0) = make_float2(v2, v3);
        }
    }
}

// ---------------- graph readout ----------------------------------------------
__global__ void count_kernel(const void* __restrict__ gid) {
    int i = blockIdx.x * blockDim.x + threadIdx.x;
    if (i >= N_NODES) return;
    int g = load_idx(gid, i, g_is64);
    atomicAdd(&g_gcnt[g], 1.0f);
}

__global__ void readout_kernel(const float* __restrict__ h,
                               const void* __restrict__ gid) {
    int t = threadIdx.x;
    int base = blockIdx.x * 128;
    int is64 = g_is64;
    int cur = load_idx(gid, base, is64);
    float acc = 0.0f;
    for (int n = 0; n < 128; n++) {
        int node = base + n;
        int g = load_idx(gid, node, is64);
        if (g != cur) {
            atomicAdd(&g_gsum[cur * HIDDEN + t], acc);
            acc = 0.0f; cur = g;
        }
        acc += h[(size_t)node * HIDDEN + t];
    }
    atomicAdd(&g_gsum[cur * HIDDEN + t], acc);
}

__global__ void classifier_kernel(const float* __restrict__ Wc,
                                  const float* __restrict__ bc,
                                  float* __restrict__ out) {
    int t = blockIdx.x * blockDim.x + threadIdx.x;
    if (t >= NUM_GRAPHS * OUTDIM) return;
    int g = t / OUTDIM, o = t % OUTDIM;
    float c = fmaxf(g_gcnt[g], 1.0f);
    float inv = 1.0f / c;
    float acc = bc[o];
#pragma unroll 8
    for (int k = 0; k < HIDDEN; k++)
        acc += g_gsum[g * HIDDEN + k] * inv * Wc[k * OUTDIM + o];
    out[t] = acc;
}

// ---------------- launch -------------------------------------------------------
extern "C" void kernel_launch(void* const* d_in, const int* in_sizes, int n_in,
                              void* d_out, int out_size) {
    const float* features = (const float*)d_in[0];
    const void*  src      = d_in[1];
    const void*  dst      = d_in[2];
    const void*  gids     = d_in[3];
    const float* W1 = (const float*)d_in[4];
    const float* b1 = (const float*)d_in[5];
    const float* W2 = (const float*)d_in[6];
    const float* b2 = (const float*)d_in[7];
    const float* W3 = (const float*)d_in[8];
    const float* b3 = (const float*)d_in[9];
    const float* Wc = (const float*)d_in[10];
    const float* bc = (const float*)d_in[11];
    float* out = (float*)d_out;

    uint32_t* ahi; cudaGetSymbolAddress((void**)&ahi, g_ahi);
    uint32_t* alo; cudaGetSymbolAddress((void**)&alo, g_alo);
    float* h;      cudaGetSymbolAddress((void**)&h, g_h);
    uint32_t* whi; cudaGetSymbolAddress((void**)&whi, g_whi);
    uint32_t* wlo; cudaGetSymbolAddress((void**)&wlo, g_wlo);

    cudaFuncSetAttribute(gemm_tc_kernel,
                         cudaFuncAttributeMaxDynamicSharedMemorySize, GEMM_SMEM_BYTES);

    detect_kernel<<<1, 1>>>((const unsigned int*)src);
    zero_kernel<<<N_NODES / 256, 256>>>();
    wprep_kernel<<<(3 * HIDDEN * 64 + 255) / 256, 256>>>(W1, W2, W3);
    build_kernel<<<N_EDGES / 1024, 256>>>(src, dst);

    const int GATHER_BLOCKS = (N_NODES * 32) / 256;
    const int GEMM_BLOCKS = N_NODES / 64;
    const int WSZ = HIDDEN * 64;

    gather_kernel<<<GATHER_BLOCKS, 256>>>(features, ahi, alo);
    gemm_tc_kernel<<<GEMM_BLOCKS, 256, GEMM_SMEM_BYTES>>>(ahi, alo, whi, wlo, b1, h);
    gather_kernel<<<GATHER_BLOCKS, 256>>>(h, ahi, alo);
    gemm_tc_kernel<<<GEMM_BLOCKS, 256, GEMM_SMEM_BYTES>>>(ahi, alo, whi + WSZ, wlo + WSZ, b2, h);
    gather_kernel<<<GATHER_BLOCKS, 256>>>(h, ahi, alo);
    gemm_tc_kernel<<<GEMM_BLOCKS, 256, GEMM_SMEM_BYTES>>>(ahi, alo, whi + 2 * WSZ, wlo + 2 * WSZ, b3, h);

    count_kernel<<<N_NODES / 256, 256>>>(gids);
    readout_kernel<<<N_NODES / 128, 128>>>(h, gids);
    classifier_kernel<<<1, NUM_GRAPHS * OUTDIM>>>(Wc, bc, out);
}

// round 6
// speedup vs baseline: 1.9813x; 1.1997x over previous
#include <cuda_runtime.h>
#include <cuda_bf16.h>
#include <math.h>
#include <stdint.h>

#define N_NODES 65536
#define N_EDGES 524288
#define HIDDEN 128
#define OUTDIM 10
#define NUM_GRAPHS 64
#define SLOT_CAP 64

// ---------------- scratch (device globals; no allocation allowed) ----------
__device__ __align__(16) static uint32_t g_ahi[(size_t)N_NODES * 64];
__device__ __align__(16) static uint32_t g_alo[(size_t)N_NODES * 64];
__device__ __align__(16) static float    g_h[(size_t)N_NODES * HIDDEN];
__device__ static int      g_deg[N_NODES];
__device__ static int      g_slots[(size_t)N_NODES * SLOT_CAP];
__device__ static float    g_gsum[NUM_GRAPHS * HIDDEN];
__device__ static float    g_gcnt[NUM_GRAPHS];
__device__ static int      g_is64;
__device__ __align__(16) static uint32_t g_whi[3][HIDDEN * 64];
__device__ __align__(16) static uint32_t g_wlo[3][HIDDEN * 64];

// ---------------- helpers ----------------------------------------------------
__device__ __forceinline__ int kperm(int w) {
    return (w & ~7) | (((w & 3) << 1) | ((w >> 2) & 1));
}

__device__ __forceinline__ void bf16_split(float v, uint16_t& h, uint16_t& l) {
    __nv_bfloat16 hb = __float2bfloat16(v);
    float r = v - __bfloat162float(hb);
    __nv_bfloat16 lb = __float2bfloat16(r);
    h = __bfloat16_as_ushort(hb);
    l = __bfloat16_as_ushort(lb);
}

__device__ __forceinline__ float elu_fast(float v) {
    return v > 0.0f ? v : (__expf(v) - 1.0f);
}

__device__ __forceinline__ void mma_bf16(float* c, uint32_t a0, uint32_t a1,
                                         uint32_t a2, uint32_t a3,
                                         uint32_t b0, uint32_t b1) {
    asm volatile(
        "mma.sync.aligned.m16n8k16.row.col.f32.bf16.bf16.f32 "
        "{%0,%1,%2,%3}, {%4,%5,%6,%7}, {%8,%9}, {%0,%1,%2,%3};"
        : "+f"(c[0]), "+f"(c[1]), "+f"(c[2]), "+f"(c[3])
        : "r"(a0), "r"(a1), "r"(a2), "r"(a3), "r"(b0), "r"(b1));
}

// ---------------- index dtype detection (1 warp, parallel) -------------------
__global__ void detect_kernel(const unsigned int* __restrict__ w) {
    int lane = threadIdx.x;
    bool zero = true;
#pragma unroll
    for (int j = 0; j < 4; j++) {
        if (w[1 + 2 * (lane + 32 * j)] != 0u) zero = false;
    }
    unsigned int mask = __ballot_sync(0xffffffffu, zero);
    if (lane == 0) g_is64 = (mask == 0xffffffffu) ? 1 : 0;
}

__device__ __forceinline__ int load_idx(const void* p, int i, int is64) {
    if (is64) return (int)((const long long*)p)[i];
    return ((const int*)p)[i];
}

// ---------------- zero scratch ----------------------------------------------
__global__ void zero_kernel() {
    int i = blockIdx.x * blockDim.x + threadIdx.x;
    if (i < N_NODES) g_deg[i] = 0;
    if (i < NUM_GRAPHS * HIDDEN) g_gsum[i] = 0.0f;
    if (i < NUM_GRAPHS) g_gcnt[i] = 0.0f;
}

// ---------------- W prep: split + transpose + k-word permute -----------------
__global__ void wprep_kernel(const float* __restrict__ W1,
                             const float* __restrict__ W2,
                             const float* __restrict__ W3) {
    int i = blockIdx.x * blockDim.x + threadIdx.x;
    if (i >= 3 * HIDDEN * 64) return;
    int layer = i / (HIDDEN * 64);
    int rem = i - layer * (HIDDEN * 64);
    int n = rem >> 6, w = rem & 63;
    const float* W = (layer == 0) ? W1 : (layer == 1) ? W2 : W3;
    float v0 = __ldg(W + (2 * w) * HIDDEN + n);
    float v1 = __ldg(W + (2 * w + 1) * HIDDEN + n);
    uint16_t h0, l0, h1, l1;
    bf16_split(v0, h0, l0);
    bf16_split(v1, h1, l1);
    int pos = n * 64 + kperm(w);
    g_whi[layer][pos] = (uint32_t)h0 | ((uint32_t)h1 << 16);
    g_wlo[layer][pos] = (uint32_t)l0 | ((uint32_t)l1 << 16);
}

// ---------------- bucketed inverse adjacency (2 edges/thread) ----------------
__global__ void build_kernel(const void* __restrict__ src,
                             const void* __restrict__ dst) {
    int base = (blockIdx.x * blockDim.x + threadIdx.x) * 2;
    if (base >= N_EDGES) return;
    int is64 = g_is64;
    int d0 = load_idx(dst, base + 0, is64), s0 = load_idx(src, base + 0, is64);
    int d1 = load_idx(dst, base + 1, is64), s1 = load_idx(src, base + 1, is64);
    int p0 = atomicAdd(&g_deg[d0], 1);
    int p1 = atomicAdd(&g_deg[d1], 1);
    if (p0 < SLOT_CAP) g_slots[(size_t)d0 * SLOT_CAP + p0] = s0;
    if (p1 < SLOT_CAP) g_slots[(size_t)d1 * SLOT_CAP + p1] = s1;
}

// ---------------- gather-sum -> bf16 hi/lo planes (k-word permuted) ----------
__global__ void gather_kernel(const float* __restrict__ hin,
                              uint32_t* __restrict__ ahi,
                              uint32_t* __restrict__ alo) {
    int w = (blockIdx.x * blockDim.x + threadIdx.x) >> 5;
    int lane = threadIdx.x & 31;
    if (w >= N_NODES) return;
    int deg = g_deg[w];
    if (deg > SLOT_CAP) deg = SLOT_CAP;
    const int* slots = g_slots + (size_t)w * SLOT_CAP;
    int s0 = (lane < deg) ? slots[lane] : 0;
    int s1 = (32 + lane < deg) ? slots[32 + lane] : 0;
    float4 acc = make_float4(0.f, 0.f, 0.f, 0.f);
    for (int i = 0; i < deg; i++) {
        int s = __shfl_sync(0xffffffffu, (i < 32) ? s0 : s1, i & 31);
        float4 v = __ldg((const float4*)(hin + (size_t)s * HIDDEN) + lane);
        acc.x += v.x; acc.y += v.y; acc.z += v.z; acc.w += v.w;
    }
    uint16_t hx, lx, hy, ly, hz, lz, hw, lw;
    bf16_split(acc.x, hx, lx);
    bf16_split(acc.y, hy, ly);
    bf16_split(acc.z, hz, lz);
    bf16_split(acc.w, hw, lw);
    size_t rowOff = (size_t)w * 64;
    int p0 = kperm(2 * lane), p1 = kperm(2 * lane + 1);
    ahi[rowOff + p0] = (uint32_t)hx | ((uint32_t)hy << 16);
    ahi[rowOff + p1] = (uint32_t)hz | ((uint32_t)hw << 16);
    alo[rowOff + p0] = (uint32_t)lx | ((uint32_t)ly << 16);
    alo[rowOff + p1] = (uint32_t)lz | ((uint32_t)lw << 16);
}

// ---------------- bf16x3 mma GEMM: 64 rows x 128 cols per CTA -----------------
#define AS_STR 68
#define SM_AH 0
#define SM_AL (64 * AS_STR)
#define SM_WH (2 * 64 * AS_STR)
#define SM_WL (2 * 64 * AS_STR + 128 * AS_STR)
#define GEMM_SMEM_WORDS (2 * 64 * AS_STR + 2 * 128 * AS_STR)
#define GEMM_SMEM_BYTES (GEMM_SMEM_WORDS * 4)

__global__ void __launch_bounds__(256, 2)
gemm_tc_kernel(const uint32_t* __restrict__ Ahi, const uint32_t* __restrict__ Alo,
               const uint32_t* __restrict__ Wh, const uint32_t* __restrict__ Wl,
               const float* __restrict__ b, float* __restrict__ out) {
    extern __shared__ __align__(16) uint32_t smem[];
    int tid = threadIdx.x;
    int lane = tid & 31, wid = tid >> 5;
    int gq = lane >> 2, tq = lane & 3;
    int warp_m = wid & 1, warp_n = wid >> 1;
    const int mBase = warp_m * 32;
    const int nBase = warp_n * 32;
    size_t rowBase = (size_t)blockIdx.x * 64;

    {
        const uint4* src_h = (const uint4*)(Ahi + rowBase * 64);
        const uint4* src_l = (const uint4*)(Alo + rowBase * 64);
        for (int i = tid; i < 64 * 16; i += 256) {
            int r = i >> 4, c4 = i & 15;
            *(uint4*)(smem + SM_AH + r * AS_STR + c4 * 4) = __ldg(src_h + i);
            *(uint4*)(smem + SM_AL + r * AS_STR + c4 * 4) = __ldg(src_l + i);
        }
    }
    {
        const uint4* src_h = (const uint4*)Wh;
        const uint4* src_l = (const uint4*)Wl;
        for (int i = tid; i < 128 * 16; i += 256) {
            int n = i >> 4, c4 = i & 15;
            *(uint4*)(smem + SM_WH + n * AS_STR + c4 * 4) = __ldg(src_h + i);
            *(uint4*)(smem + SM_WL + n * AS_STR + c4 * 4) = __ldg(src_l + i);
        }
    }
    __syncthreads();

    float acc[2][4][4];
#pragma unroll
    for (int mi = 0; mi < 2; mi++)
#pragma unroll
        for (int ni = 0; ni < 4; ni++)
#pragma unroll
            for (int r = 0; r < 4; r++) acc[mi][ni][r] = 0.0f;

#pragma unroll
    for (int ks = 0; ks < 8; ks++) {
        int kw = ks * 8 + 2 * tq;
        uint2 ah[2][2], al[2][2];
#pragma unroll
        for (int mi = 0; mi < 2; mi++) {
            int r = mBase + mi * 16 + gq;
            ah[mi][0] = *(const uint2*)(smem + SM_AH + r * AS_STR + kw);
            ah[mi][1] = *(const uint2*)(smem + SM_AH + (r + 8) * AS_STR + kw);
            al[mi][0] = *(const uint2*)(smem + SM_AL + r * AS_STR + kw);
            al[mi][1] = *(const uint2*)(smem + SM_AL + (r + 8) * AS_STR + kw);
        }
        uint2 bh[4], bl[4];
#pragma unroll
        for (int ni = 0; ni < 4; ni++) {
            int c = nBase + ni * 8 + gq;
            bh[ni] = *(const uint2*)(smem + SM_WH + c * AS_STR + kw);
            bl[ni] = *(const uint2*)(smem + SM_WL + c * AS_STR + kw);
        }
#pragma unroll
        for (int mi = 0; mi < 2; mi++)
#pragma unroll
            for (int ni = 0; ni < 4; ni++) {
                mma_bf16(acc[mi][ni], ah[mi][0].x, ah[mi][1].x, ah[mi][0].y, ah[mi][1].y,
                         bh[ni].x, bh[ni].y);
                mma_bf16(acc[mi][ni], ah[mi][0].x, ah[mi][1].x, ah[mi][0].y, ah[mi][1].y,
                         bl[ni].x, bl[ni].y);
                mma_bf16(acc[mi][ni], al[mi][0].x, al[mi][1].x, al[mi][0].y, al[mi][1].y,
                         bh[ni].x, bh[ni].y);
            }
    }

    // ---- epilogue: bias + fast ELU + store ----
#pragma unroll
    for (int mi = 0; mi < 2; mi++) {
        int r0 = mBase + mi * 16 + gq;
#pragma unroll
        for (int ni = 0; ni < 4; ni++) {
            int c0 = nBase + ni * 8 + 2 * tq;
            float2 bb = __ldg((const float2*)(b + c0));
            float v0 = elu_fast(acc[mi][ni][0] + bb.x);
            float v1 = elu_fast(acc[mi][ni][1] + bb.y);
            float v2 = elu_fast(acc[mi][ni][2] + bb.x);
            float v3 = elu_fast(acc[mi][ni][3] + bb.y);
            *(float2*)(out + (rowBase + r0) * HIDDEN + c0) = make_float2(v0, v1);
            *(float2*)(out + (rowBase + r0 + 8) * HIDDEN + c0) = make_float2(v2, v3);
        }
    }
}

// ---------------- graph readout (sums + counts fused) -------------------------
__global__ void readout_kernel(const float* __restrict__ h,
                               const void* __restrict__ gid) {
    int t = threadIdx.x;
    int base = blockIdx.x * 128;
    int is64 = g_is64;
    int cur = load_idx(gid, base, is64);
    float acc = 0.0f;
    int runlen = 0;
    for (int n = 0; n < 128; n++) {
        int node = base + n;
        int g = load_idx(gid, node, is64);
        if (g != cur) {
            atomicAdd(&g_gsum[cur * HIDDEN + t], acc);
            if (t == 0) atomicAdd(&g_gcnt[cur], (float)runlen);
            acc = 0.0f; runlen = 0; cur = g;
        }
        acc += h[(size_t)node * HIDDEN + t];
        runlen++;
    }
    atomicAdd(&g_gsum[cur * HIDDEN + t], acc);
    if (t == 0) atomicAdd(&g_gcnt[cur], (float)runlen);
}

__global__ void classifier_kernel(const float* __restrict__ Wc,
                                  const float* __restrict__ bc,
                                  float* __restrict__ out) {
    int t = blockIdx.x * blockDim.x + threadIdx.x;
    if (t >= NUM_GRAPHS * OUTDIM) return;
    int g = t / OUTDIM, o = t % OUTDIM;
    float c = fmaxf(g_gcnt[g], 1.0f);
    float inv = 1.0f / c;
    float acc = bc[o];
#pragma unroll 8
    for (int k = 0; k < HIDDEN; k++)
        acc += g_gsum[g * HIDDEN + k] * inv * Wc[k * OUTDIM + o];
    out[t] = acc;
}

// ---------------- launch -------------------------------------------------------
extern "C" void kernel_launch(void* const* d_in, const int* in_sizes, int n_in,
                              void* d_out, int out_size) {
    const float* features = (const float*)d_in[0];
    const void*  src      = d_in[1];
    const void*  dst      = d_in[2];
    const void*  gids     = d_in[3];
    const float* W1 = (const float*)d_in[4];
    const float* b1 = (const float*)d_in[5];
    const float* W2 = (const float*)d_in[6];
    const float* b2 = (const float*)d_in[7];
    const float* W3 = (const float*)d_in[8];
    const float* b3 = (const float*)d_in[9];
    const float* Wc = (const float*)d_in[10];
    const float* bc = (const float*)d_in[11];
    float* out = (float*)d_out;

    uint32_t* ahi; cudaGetSymbolAddress((void**)&ahi, g_ahi);
    uint32_t* alo; cudaGetSymbolAddress((void**)&alo, g_alo);
    float* h;      cudaGetSymbolAddress((void**)&h, g_h);
    uint32_t* whi; cudaGetSymbolAddress((void**)&whi, g_whi);
    uint32_t* wlo; cudaGetSymbolAddress((void**)&wlo, g_wlo);

    cudaFuncSetAttribute(gemm_tc_kernel,
                         cudaFuncAttributeMaxDynamicSharedMemorySize, GEMM_SMEM_BYTES);

    detect_kernel<<<1, 32>>>((const unsigned int*)src);
    zero_kernel<<<N_NODES / 256, 256>>>();
    wprep_kernel<<<(3 * HIDDEN * 64 + 255) / 256, 256>>>(W1, W2, W3);
    build_kernel<<<N_EDGES / 512, 256>>>(src, dst);

    const int GATHER_BLOCKS = (N_NODES * 32) / 256;
    const int GEMM_BLOCKS = N_NODES / 64;
    const int WSZ = HIDDEN * 64;

    gather_kernel<<<GATHER_BLOCKS, 256>>>(features, ahi, alo);
    gemm_tc_kernel<<<GEMM_BLOCKS, 256, GEMM_SMEM_BYTES>>>(ahi, alo, whi, wlo, b1, h);
    gather_kernel<<<GATHER_BLOCKS, 256>>>(h, ahi, alo);
    gemm_tc_kernel<<<GEMM_BLOCKS, 256, GEMM_SMEM_BYTES>>>(ahi, alo, whi + WSZ, wlo + WSZ, b2, h);
    gather_kernel<<<GATHER_BLOCKS, 256>>>(h, ahi, alo);
    gemm_tc_kernel<<<GEMM_BLOCKS, 256, GEMM_SMEM_BYTES>>>(ahi, alo, whi + 2 * WSZ, wlo + 2 * WSZ, b3, h);

    readout_kernel<<<N_NODES / 128, 128>>>(h, gids);
    classifier_kernel<<<1, NUM_GRAPHS * OUTDIM>>>(Wc, bc, out);
}

// round 7
// speedup vs baseline: 2.2027x; 1.1117x over previous
#include <cuda_runtime.h>
#include <cuda_bf16.h>
#include <math.h>
#include <stdint.h>

#define N_NODES 65536
#define N_EDGES 524288
#define HIDDEN 128
#define OUTDIM 10
#define NUM_GRAPHS 64
#define SLOT_CAP 64

// ---------------- scratch (device globals; no allocation allowed) ----------
__device__ __align__(16) static uint32_t g_ahi[(size_t)N_NODES * 64];
__device__ __align__(16) static uint32_t g_alo[(size_t)N_NODES * 64];
__device__ __align__(16) static float    g_h[(size_t)N_NODES * HIDDEN];
__device__ static int      g_deg[N_NODES];
__device__ static int      g_slots[(size_t)N_NODES * SLOT_CAP];
__device__ static float    g_gsum[NUM_GRAPHS * HIDDEN];
__device__ static float    g_gcnt[NUM_GRAPHS];
__device__ static int      g_is64;
__device__ __align__(16) static uint32_t g_whi[3][HIDDEN * 64];
__device__ __align__(16) static uint32_t g_wlo[3][HIDDEN * 64];

// ---------------- helpers ----------------------------------------------------
__device__ __forceinline__ int kperm(int w) {
    return (w & ~7) | (((w & 3) << 1) | ((w >> 2) & 1));
}

__device__ __forceinline__ void bf16_split(float v, uint16_t& h, uint16_t& l) {
    __nv_bfloat16 hb = __float2bfloat16(v);
    float r = v - __bfloat162float(hb);
    __nv_bfloat16 lb = __float2bfloat16(r);
    h = __bfloat16_as_ushort(hb);
    l = __bfloat16_as_ushort(lb);
}

__device__ __forceinline__ float elu_fast(float v) {
    return v > 0.0f ? v : (__expf(v) - 1.0f);
}

__device__ __forceinline__ void mma_bf16(float* c, uint32_t a0, uint32_t a1,
                                         uint32_t a2, uint32_t a3,
                                         uint32_t b0, uint32_t b1) {
    asm volatile(
        "mma.sync.aligned.m16n8k16.row.col.f32.bf16.bf16.f32 "
        "{%0,%1,%2,%3}, {%4,%5,%6,%7}, {%8,%9}, {%0,%1,%2,%3};"
        : "+f"(c[0]), "+f"(c[1]), "+f"(c[2]), "+f"(c[3])
        : "r"(a0), "r"(a1), "r"(a2), "r"(a3), "r"(b0), "r"(b1));
}

// ---------------- index dtype detection (1 warp, parallel) -------------------
__global__ void detect_kernel(const unsigned int* __restrict__ w) {
    int lane = threadIdx.x;
    bool zero = true;
#pragma unroll
    for (int j = 0; j < 4; j++) {
        if (w[1 + 2 * (lane + 32 * j)] != 0u) zero = false;
    }
    unsigned int mask = __ballot_sync(0xffffffffu, zero);
    if (lane == 0) g_is64 = (mask == 0xffffffffu) ? 1 : 0;
}

__device__ __forceinline__ int load_idx(const void* p, int i, int is64) {
    if (is64) return (int)((const long long*)p)[i];
    return ((const int*)p)[i];
}

// ---------------- prep: zero scratch + W split (fused) ------------------------
__global__ void prep_kernel(const float* __restrict__ W1,
                            const float* __restrict__ W2,
                            const float* __restrict__ W3) {
    int i = blockIdx.x * blockDim.x + threadIdx.x;
    if (i < N_NODES) g_deg[i] = 0;
    if (i < NUM_GRAPHS * HIDDEN) g_gsum[i] = 0.0f;
    if (i < NUM_GRAPHS) g_gcnt[i] = 0.0f;
    if (i < 3 * HIDDEN * 64) {
        int layer = i / (HIDDEN * 64);
        int rem = i - layer * (HIDDEN * 64);
        int n = rem >> 6, w = rem & 63;
        const float* W = (layer == 0) ? W1 : (layer == 1) ? W2 : W3;
        float v0 = __ldg(W + (2 * w) * HIDDEN + n);
        float v1 = __ldg(W + (2 * w + 1) * HIDDEN + n);
        uint16_t h0, l0, h1, l1;
        bf16_split(v0, h0, l0);
        bf16_split(v1, h1, l1);
        int pos = n * 64 + kperm(w);
        g_whi[layer][pos] = (uint32_t)h0 | ((uint32_t)h1 << 16);
        g_wlo[layer][pos] = (uint32_t)l0 | ((uint32_t)l1 << 16);
    }
}

// ---------------- bucketed inverse adjacency (2 edges/thread) ----------------
__global__ void build_kernel(const void* __restrict__ src,
                             const void* __restrict__ dst) {
    int base = (blockIdx.x * blockDim.x + threadIdx.x) * 2;
    if (base >= N_EDGES) return;
    int is64 = g_is64;
    int d0 = load_idx(dst, base + 0, is64), s0 = load_idx(src, base + 0, is64);
    int d1 = load_idx(dst, base + 1, is64), s1 = load_idx(src, base + 1, is64);
    int p0 = atomicAdd(&g_deg[d0], 1);
    int p1 = atomicAdd(&g_deg[d1], 1);
    if (p0 < SLOT_CAP) g_slots[(size_t)d0 * SLOT_CAP + p0] = s0;
    if (p1 < SLOT_CAP) g_slots[(size_t)d1 * SLOT_CAP + p1] = s1;
}

// ---------------- gather-sum -> bf16 hi/lo planes (k-word permuted) ----------
__global__ void gather_kernel(const float* __restrict__ hin,
                              uint32_t* __restrict__ ahi,
                              uint32_t* __restrict__ alo) {
    int w = (blockIdx.x * blockDim.x + threadIdx.x) >> 5;
    int lane = threadIdx.x & 31;
    if (w >= N_NODES) return;
    int deg = g_deg[w];
    if (deg > SLOT_CAP) deg = SLOT_CAP;
    const int* slots = g_slots + (size_t)w * SLOT_CAP;
    int s0 = (lane < deg) ? slots[lane] : 0;
    int s1 = (32 + lane < deg) ? slots[32 + lane] : 0;
    float4 accA = make_float4(0.f, 0.f, 0.f, 0.f);
    float4 accB = make_float4(0.f, 0.f, 0.f, 0.f);
    int i = 0;
    for (; i + 4 <= deg; i += 4) {
        int sa = __shfl_sync(0xffffffffu, (i < 32) ? s0 : s1, i & 31);
        int sb = __shfl_sync(0xffffffffu, (i + 1 < 32) ? s0 : s1, (i + 1) & 31);
        int sc = __shfl_sync(0xffffffffu, (i + 2 < 32) ? s0 : s1, (i + 2) & 31);
        int sd = __shfl_sync(0xffffffffu, (i + 3 < 32) ? s0 : s1, (i + 3) & 31);
        float4 va = __ldg((const float4*)(hin + (size_t)sa * HIDDEN) + lane);
        float4 vb = __ldg((const float4*)(hin + (size_t)sb * HIDDEN) + lane);
        float4 vc = __ldg((const float4*)(hin + (size_t)sc * HIDDEN) + lane);
        float4 vd = __ldg((const float4*)(hin + (size_t)sd * HIDDEN) + lane);
        accA.x += va.x; accA.y += va.y; accA.z += va.z; accA.w += va.w;
        accB.x += vb.x; accB.y += vb.y; accB.z += vb.z; accB.w += vb.w;
        accA.x += vc.x; accA.y += vc.y; accA.z += vc.z; accA.w += vc.w;
        accB.x += vd.x; accB.y += vd.y; accB.z += vd.z; accB.w += vd.w;
    }
    for (; i < deg; i++) {
        int s = __shfl_sync(0xffffffffu, (i < 32) ? s0 : s1, i & 31);
        float4 v = __ldg((const float4*)(hin + (size_t)s * HIDDEN) + lane);
        accA.x += v.x; accA.y += v.y; accA.z += v.z; accA.w += v.w;
    }
    float4 acc = make_float4(accA.x + accB.x, accA.y + accB.y,
                             accA.z + accB.z, accA.w + accB.w);
    uint16_t hx, lx, hy, ly, hz, lz, hw, lw;
    bf16_split(acc.x, hx, lx);
    bf16_split(acc.y, hy, ly);
    bf16_split(acc.z, hz, lz);
    bf16_split(acc.w, hw, lw);
    size_t rowOff = (size_t)w * 64;
    int p0 = kperm(2 * lane), p1 = kperm(2 * lane + 1);
    ahi[rowOff + p0] = (uint32_t)hx | ((uint32_t)hy << 16);
    ahi[rowOff + p1] = (uint32_t)hz | ((uint32_t)hw << 16);
    alo[rowOff + p0] = (uint32_t)lx | ((uint32_t)ly << 16);
    alo[rowOff + p1] = (uint32_t)lz | ((uint32_t)lw << 16);
}

// ---------------- persistent bf16x3 mma GEMM ----------------------------------
// 296 CTAs, each loops over M-tiles (64 rows x 128 cols). W staged once.
// A staging pipelined: LDG prefetch of tile t+1 overlaps mainloop of tile t.
#define AS_STR 68
#define SM_AH 0
#define SM_AL (64 * AS_STR)
#define SM_WH (2 * 64 * AS_STR)
#define SM_WL (2 * 64 * AS_STR + 128 * AS_STR)
#define GEMM_SMEM_WORDS (2 * 64 * AS_STR + 2 * 128 * AS_STR)
#define GEMM_SMEM_BYTES (GEMM_SMEM_WORDS * 4)
#define GEMM_GRID 296
#define NUM_TILES (N_NODES / 64)

__global__ void __launch_bounds__(256, 2)
gemm_tc_kernel(const uint32_t* __restrict__ Ahi, const uint32_t* __restrict__ Alo,
               const uint32_t* __restrict__ Wh, const uint32_t* __restrict__ Wl,
               const float* __restrict__ b, float* __restrict__ out) {
    extern __shared__ __align__(16) uint32_t smem[];
    int tid = threadIdx.x;
    int lane = tid & 31, wid = tid >> 5;
    int gq = lane >> 2, tq = lane & 3;
    int warp_m = wid & 1, warp_n = wid >> 1;
    const int mBase = warp_m * 32;
    const int nBase = warp_n * 32;

    // ---- stage W planes once ----
    {
        const uint4* src_h = (const uint4*)Wh;
        const uint4* src_l = (const uint4*)Wl;
        for (int i = tid; i < 128 * 16; i += 256) {
            int n = i >> 4, c4 = i & 15;
            *(uint4*)(smem + SM_WH + n * AS_STR + c4 * 4) = __ldg(src_h + i);
            *(uint4*)(smem + SM_WL + n * AS_STR + c4 * 4) = __ldg(src_l + i);
        }
    }

    int tile = blockIdx.x;
    uint4 pa[4], pl[4];
    if (tile < NUM_TILES) {
        const uint4* src_h = (const uint4*)(Ahi + (size_t)tile * 64 * 64);
        const uint4* src_l = (const uint4*)(Alo + (size_t)tile * 64 * 64);
#pragma unroll
        for (int j = 0; j < 4; j++) {
            pa[j] = __ldg(src_h + tid + 256 * j);
            pl[j] = __ldg(src_l + tid + 256 * j);
        }
    }
    __syncthreads();   // W staged; A smem untouched yet

    while (tile < NUM_TILES) {
        // ---- commit prefetched A to SMEM ----
#pragma unroll
        for (int j = 0; j < 4; j++) {
            int i = tid + 256 * j;
            int r = i >> 4, c4 = i & 15;
            *(uint4*)(smem + SM_AH + r * AS_STR + c4 * 4) = pa[j];
            *(uint4*)(smem + SM_AL + r * AS_STR + c4 * 4) = pl[j];
        }
        __syncthreads();

        // ---- prefetch next tile's A (overlaps mainloop) ----
        int next = tile + GEMM_GRID;
        if (next < NUM_TILES) {
            const uint4* src_h = (const uint4*)(Ahi + (size_t)next * 64 * 64);
            const uint4* src_l = (const uint4*)(Alo + (size_t)next * 64 * 64);
#pragma unroll
            for (int j = 0; j < 4; j++) {
                pa[j] = __ldg(src_h + tid + 256 * j);
                pl[j] = __ldg(src_l + tid + 256 * j);
            }
        }

        float acc[2][4][4];
#pragma unroll
        for (int mi = 0; mi < 2; mi++)
#pragma unroll
            for (int ni = 0; ni < 4; ni++)
#pragma unroll
                for (int r = 0; r < 4; r++) acc[mi][ni][r] = 0.0f;

#pragma unroll
        for (int ks = 0; ks < 8; ks++) {
            int kw = ks * 8 + 2 * tq;
            uint2 ah[2][2], al[2][2];
#pragma unroll
            for (int mi = 0; mi < 2; mi++) {
                int r = mBase + mi * 16 + gq;
                ah[mi][0] = *(const uint2*)(smem + SM_AH + r * AS_STR + kw);
                ah[mi][1] = *(const uint2*)(smem + SM_AH + (r + 8) * AS_STR + kw);
                al[mi][0] = *(const uint2*)(smem + SM_AL + r * AS_STR + kw);
                al[mi][1] = *(const uint2*)(smem + SM_AL + (r + 8) * AS_STR + kw);
            }
            uint2 bh[4], bl[4];
#pragma unroll
            for (int ni = 0; ni < 4; ni++) {
                int c = nBase + ni * 8 + gq;
                bh[ni] = *(const uint2*)(smem + SM_WH + c * AS_STR + kw);
                bl[ni] = *(const uint2*)(smem + SM_WL + c * AS_STR + kw);
            }
#pragma unroll
            for (int mi = 0; mi < 2; mi++)
#pragma unroll
                for (int ni = 0; ni < 4; ni++) {
                    mma_bf16(acc[mi][ni], ah[mi][0].x, ah[mi][1].x, ah[mi][0].y, ah[mi][1].y,
                             bh[ni].x, bh[ni].y);
                    mma_bf16(acc[mi][ni], ah[mi][0].x, ah[mi][1].x, ah[mi][0].y, ah[mi][1].y,
                             bl[ni].x, bl[ni].y);
                    mma_bf16(acc[mi][ni], al[mi][0].x, al[mi][1].x, al[mi][0].y, al[mi][1].y,
                             bh[ni].x, bh[ni].y);
                }
        }

        // ---- epilogue: bias + fast ELU + store ----
        size_t rowBase = (size_t)tile * 64;
#pragma unroll
        for (int mi = 0; mi < 2; mi++) {
            int r0 = mBase + mi * 16 + gq;
#pragma unroll
            for (int ni = 0; ni < 4; ni++) {
                int c0 = nBase + ni * 8 + 2 * tq;
                float2 bb = __ldg((const float2*)(b + c0));
                float v0 = elu_fast(acc[mi][ni][0] + bb.x);
                float v1 = elu_fast(acc[mi][ni][1] + bb.y);
                float v2 = elu_fast(acc[mi][ni][2] + bb.x);
                float v3 = elu_fast(acc[mi][ni][3] + bb.y);
                *(float2*)(out + (rowBase + r0) * HIDDEN + c0) = make_float2(v0, v1);
                *(float2*)(out + (rowBase + r0 + 8) * HIDDEN + c0) = make_float2(v2, v3);
            }
        }
        __syncthreads();   // A smem free for next STS
        tile = next;
    }
}

// ---------------- graph readout (sums + counts fused) -------------------------
__global__ void readout_kernel(const float* __restrict__ h,
                               const void* __restrict__ gid) {
    int t = threadIdx.x;
    int base = blockIdx.x * 128;
    int is64 = g_is64;
    int cur = load_idx(gid, base, is64);
    float acc = 0.0f;
    int runlen = 0;
    for (int n = 0; n < 128; n++) {
        int node = base + n;
        int g = load_idx(gid, node, is64);
        if (g != cur) {
            atomicAdd(&g_gsum[cur * HIDDEN + t], acc);
            if (t == 0) atomicAdd(&g_gcnt[cur], (float)runlen);
            acc = 0.0f; runlen = 0; cur = g;
        }
        acc += h[(size_t)node * HIDDEN + t];
        runlen++;
    }
    atomicAdd(&g_gsum[cur * HIDDEN + t], acc);
    if (t == 0) atomicAdd(&g_gcnt[cur], (float)runlen);
}

__global__ void classifier_kernel(const float* __restrict__ Wc,
                                  const float* __restrict__ bc,
                                  float* __restrict__ out) {
    int t = blockIdx.x * blockDim.x + threadIdx.x;
    if (t >= NUM_GRAPHS * OUTDIM) return;
    int g = t / OUTDIM, o = t % OUTDIM;
    float c = fmaxf(g_gcnt[g], 1.0f);
    float inv = 1.0f / c;
    float acc = bc[o];
#pragma unroll 8
    for (int k = 0; k < HIDDEN; k++)
        acc += g_gsum[g * HIDDEN + k] * inv * Wc[k * OUTDIM + o];
    out[t] = acc;
}

// ---------------- launch -------------------------------------------------------
extern "C" void kernel_launch(void* const* d_in, const int* in_sizes, int n_in,
                              void* d_out, int out_size) {
    const float* features = (const float*)d_in[0];
    const void*  src      = d_in[1];
    const void*  dst      = d_in[2];
    const void*  gids     = d_in[3];
    const float* W1 = (const float*)d_in[4];
    const float* b1 = (const float*)d_in[5];
    const float* W2 = (const float*)d_in[6];
    const float* b2 = (const float*)d_in[7];
    const float* W3 = (const float*)d_in[8];
    const float* b3 = (const float*)d_in[9];
    const float* Wc = (const float*)d_in[10];
    const float* bc = (const float*)d_in[11];
    float* out = (float*)d_out;

    uint32_t* ahi; cudaGetSymbolAddress((void**)&ahi, g_ahi);
    uint32_t* alo; cudaGetSymbolAddress((void**)&alo, g_alo);
    float* h;      cudaGetSymbolAddress((void**)&h, g_h);
    uint32_t* whi; cudaGetSymbolAddress((void**)&whi, g_whi);
    uint32_t* wlo; cudaGetSymbolAddress((void**)&wlo, g_wlo);

    cudaFuncSetAttribute(gemm_tc_kernel,
                         cudaFuncAttributeMaxDynamicSharedMemorySize, GEMM_SMEM_BYTES);

    detect_kernel<<<1, 32>>>((const unsigned int*)src);
    prep_kernel<<<N_NODES / 256, 256>>>(W1, W2, W3);
    build_kernel<<<N_EDGES / 512, 256>>>(src, dst);

    const int GATHER_BLOCKS = (N_NODES * 32) / 256;
    const int WSZ = HIDDEN * 64;

    gather_kernel<<<GATHER_BLOCKS, 256>>>(features, ahi, alo);
    gemm_tc_kernel<<<GEMM_GRID, 256, GEMM_SMEM_BYTES>>>(ahi, alo, whi, wlo, b1, h);
    gather_kernel<<<GATHER_BLOCKS, 256>>>(h, ahi, alo);
    gemm_tc_kernel<<<GEMM_GRID, 256, GEMM_SMEM_BYTES>>>(ahi, alo, whi + WSZ, wlo + WSZ, b2, h);
    gather_kernel<<<GATHER_BLOCKS, 256>>>(h, ahi, alo);
    gemm_tc_kernel<<<GEMM_GRID, 256, GEMM_SMEM_BYTES>>>(ahi, alo, whi + 2 * WSZ, wlo + 2 * WSZ, b3, h);

    readout_kernel<<<N_NODES / 128, 128>>>(h, gids);
    classifier_kernel<<<1, NUM_GRAPHS * OUTDIM>>>(Wc, bc, out);
}